// round 12
// baseline (speedup 1.0000x reference)
#include <cuda_runtime.h>
#include <cuda_fp16.h>
#include <cstdint>

#define BATCH   4
#define T_SEQ   64
#define NSPAT   196
#define CDIM    768
#define HEADS   12
#define HD      64
#define M_TOT   (BATCH * T_SEQ * NSPAT)   // 50176
#define QKV_N   (3 * CDIM)                // 2304

// Scratch (device globals: allocation-free per harness rules)
__device__ __half g_qkv[(size_t)M_TOT * QKV_N];  // 231 MB
__device__ __half g_att[(size_t)M_TOT * CDIM];   // 77 MB
__device__ __half g_xh [(size_t)M_TOT * CDIM];   // 77 MB  (fp16 x)
__device__ __half g_wqh[(size_t)QKV_N * CDIM];   // fp16 w_qkv
__device__ __half g_wph[(size_t)CDIM * CDIM];    // fp16 w_proj

// ---------------------------------------------------------------------------
// helpers
// ---------------------------------------------------------------------------
__device__ __forceinline__ void cp_async16(uint32_t saddr, const void* gptr) {
    asm volatile("cp.async.cg.shared.global [%0], [%1], 16;\n" :: "r"(saddr), "l"(gptr));
}
__device__ __forceinline__ void cp_commit() {
    asm volatile("cp.async.commit_group;\n" ::: "memory");
}
__device__ __forceinline__ void cp_wait1() {
    asm volatile("cp.async.wait_group 1;\n" ::: "memory");
}
// D += A*B  (m16n8k16 fp16 inputs, fp32 accum)
__device__ __forceinline__ void mma16816(float* d, const uint32_t* a, const uint32_t* b) {
    asm volatile(
        "mma.sync.aligned.m16n8k16.row.col.f32.f16.f16.f32 "
        "{%0,%1,%2,%3}, {%4,%5,%6,%7}, {%8,%9}, {%0,%1,%2,%3};"
        : "+f"(d[0]), "+f"(d[1]), "+f"(d[2]), "+f"(d[3])
        : "r"(a[0]), "r"(a[1]), "r"(a[2]), "r"(a[3]), "r"(b[0]), "r"(b[1]));
}
// 4x 8x8 b16 matrices from shared
__device__ __forceinline__ void ldmx4(uint32_t& r0, uint32_t& r1, uint32_t& r2, uint32_t& r3,
                                      uint32_t saddr) {
    asm volatile("ldmatrix.sync.aligned.m8n8.x4.shared.b16 {%0,%1,%2,%3}, [%4];"
                 : "=r"(r0), "=r"(r1), "=r"(r2), "=r"(r3) : "r"(saddr));
}

// ---------------------------------------------------------------------------
// FP16 MMA GEMM: C[m][n] = sum_k A[m*K+k] * B[n*K+k] (+ bias[n])
// Block 256(m) x 128(n), BK=64, 3-stage cp.async, 256 threads = 8 warps (4x2),
// warp tile 64x64; fragments via ldmatrix.x4, double-buffered.
// One barrier per K-block (top-of-loop barrier also protects slot refill).
// ---------------------------------------------------------------------------
#define GBM 256
#define GBN 128
#define GBK 64
#define G_ROWB 144                               // bytes per smem row
#define STAGE_BYTES ((GBM + GBN) * G_ROWB)       // 55,296 B
#define G_STAGES 3
#define G_SMEM (G_STAGES * STAGE_BYTES)          // 165,888 B

template<bool HALF_OUT>
__global__ void __launch_bounds__(256, 1) gemm_h_kernel(
    const __half* __restrict__ A, const __half* __restrict__ B,
    void* __restrict__ Cv, const float* __restrict__ bias,
    int M, int N, int K)
{
    extern __shared__ char smem[];
    const uint32_t sbase = (uint32_t)__cvta_generic_to_shared(smem);

    const int n0 = blockIdx.x * GBN;     // N fastest -> weights L2-resident
    const int m0 = blockIdx.y * GBM;

    const int tid  = threadIdx.x;
    const int warp = tid >> 5;
    const int lane = tid & 31;
    const int wm   = warp >> 1;          // 0..3 -> rows wm*64
    const int wn   = warp & 1;           // 0..1 -> cols wn*64
    const int g    = lane >> 2;          // 0..7
    const int t    = lane & 3;           // 0..3
    const int quad = lane >> 3;          // 0..3 (ldmatrix address group)
    const int qr   = lane & 7;           // row within group

    // per-thread intra-stage ldmatrix offsets
    const uint32_t a_off = (uint32_t)((wm * 64 + (quad & 1) * 8 + qr) * G_ROWB
                                      + (quad >> 1) * 16);
    const uint32_t b_off = (uint32_t)(GBM * G_ROWB
                                      + (wn * 64 + (quad >> 1) * 8 + qr) * G_ROWB
                                      + (quad & 1) * 16);

    float acc[4][8][4];
    #pragma unroll
    for (int i = 0; i < 4; i++)
        #pragma unroll
        for (int j = 0; j < 8; j++)
            #pragma unroll
            for (int c = 0; c < 4; c++)
                acc[i][j][c] = 0.0f;

    const int NB = K / GBK;              // 12

    // stage loader: 384 rows x 8 chunks(16B) = 3072, 12 per thread
    auto issue_stage = [&](int kb, int s) {
        char* dst = smem + s * STAGE_BYTES;
        #pragma unroll
        for (int i = 0; i < 12; i++) {
            int id = tid + i * 256;              // 0..3071
            int r  = id >> 3;                    // 0..383
            int c  = id & 7;                     // 0..7 (8 halves each)
            const __half* gp = (r < GBM)
                ? A + (size_t)(m0 + r) * K + kb * GBK + c * 8
                : B + (size_t)(n0 + r - GBM) * K + kb * GBK + c * 8;
            uint32_t sa = (uint32_t)__cvta_generic_to_shared(dst + r * G_ROWB + c * 16);
            cp_async16(sa, gp);
        }
    };

    auto load_a = [&](uint32_t stg, int ks, uint32_t a[4][4]) {
        #pragma unroll
        for (int mf = 0; mf < 4; mf++)
            ldmx4(a[mf][0], a[mf][1], a[mf][2], a[mf][3],
                  stg + a_off + (uint32_t)(mf * 16 * G_ROWB + ks * 32));
    };
    auto load_b = [&](uint32_t stg, int ks, uint32_t b[8][2]) {
        #pragma unroll
        for (int p = 0; p < 4; p++)
            ldmx4(b[2 * p][0], b[2 * p][1], b[2 * p + 1][0], b[2 * p + 1][1],
                  stg + b_off + (uint32_t)(p * 16 * G_ROWB + ks * 32));
    };

    issue_stage(0, 0); cp_commit();
    issue_stage(1, 1); cp_commit();

    for (int kb = 0; kb < NB; kb++) {
        cp_wait1();            // stage kb resident
        __syncthreads();       // also orders: all warps done reading slot kb%3's
                               // previous contents before the refill below

        if (kb + 2 < NB) issue_stage(kb + 2, (kb + 2) % 3);
        cp_commit();           // one group per iteration

        const uint32_t stg = sbase + (uint32_t)((kb % 3) * STAGE_BYTES);

        uint32_t a0[4][4], b0[8][2], a1[4][4], b1[8][2];
        load_a(stg, 0, a0); load_b(stg, 0, b0);

        #pragma unroll
        for (int ks = 0; ks < 4; ks += 2) {
            if (ks + 1 < 4) { load_a(stg, ks + 1, a1); load_b(stg, ks + 1, b1); }
            #pragma unroll
            for (int mf = 0; mf < 4; mf++)
                #pragma unroll
                for (int nf = 0; nf < 8; nf++)
                    mma16816(acc[mf][nf], a0[mf], b0[nf]);
            if (ks + 2 < 4) { load_a(stg, ks + 2, a0); load_b(stg, ks + 2, b0); }
            if (ks + 1 < 4) {
                #pragma unroll
                for (int mf = 0; mf < 4; mf++)
                    #pragma unroll
                    for (int nf = 0; nf < 8; nf++)
                        mma16816(acc[mf][nf], a1[mf], b1[nf]);
            }
        }
        // no second barrier: next iteration's top barrier provides the ordering
    }

    // epilogue: fused bias; half2 or float2 stores
    #pragma unroll
    for (int nf = 0; nf < 8; nf++) {
        int col = n0 + wn * 64 + nf * 8 + 2 * t;
        float bx = 0.0f, by = 0.0f;
        if (bias) { float2 bv = *(const float2*)&bias[col]; bx = bv.x; by = bv.y; }
        #pragma unroll
        for (int mf = 0; mf < 4; mf++) {
            int row = m0 + wm * 64 + mf * 16 + g;
            if (HALF_OUT) {
                __half* Ch = (__half*)Cv;
                *(__half2*)&Ch[(size_t)row * N + col] =
                    __floats2half2_rn(acc[mf][nf][0] + bx, acc[mf][nf][1] + by);
                *(__half2*)&Ch[(size_t)(row + 8) * N + col] =
                    __floats2half2_rn(acc[mf][nf][2] + bx, acc[mf][nf][3] + by);
            } else {
                float* Cf = (float*)Cv;
                *(float2*)&Cf[(size_t)row * N + col] =
                    make_float2(acc[mf][nf][0] + bx, acc[mf][nf][1] + by);
                *(float2*)&Cf[(size_t)(row + 8) * N + col] =
                    make_float2(acc[mf][nf][2] + bx, acc[mf][nf][3] + by);
            }
        }
    }
}

// ---------------------------------------------------------------------------
// fp32 -> fp16 conversion prepass
// ---------------------------------------------------------------------------
__global__ void __launch_bounds__(256) f2h_kernel(
    const float* __restrict__ in, __half* __restrict__ out, size_t n4)
{
    size_t i = (size_t)blockIdx.x * 256 + threadIdx.x;
    if (i < n4) {
        float4 v = ((const float4*)in)[i];
        ((__half2*)out)[2 * i + 0] = __floats2half2_rn(v.x, v.y);
        ((__half2*)out)[2 * i + 1] = __floats2half2_rn(v.z, v.w);
    }
}

// ---------------------------------------------------------------------------
// FP16 MMA causal attention per (b,h,n): T=64, hd=64.
// 128 threads = 4 warps; warp w owns query rows 16w..16w+15.
// ---------------------------------------------------------------------------
#define ALDH 72                       // halves per smem row
#define ALDW 36                       // words per row
#define ATTN_SMEM (3 * 64 * ALDH * 2) // 27,648 B

__global__ void __launch_bounds__(128) attn_mma_kernel(
    const __half* __restrict__ qkv, __half* __restrict__ att)
{
    extern __shared__ char smc[];
    __half* sQ  = (__half*)smc;              // [q][d]; reused as sP [q][j]
    __half* sK  = sQ + 64 * ALDH;            // [key][d]
    __half* sVt = sQ + 2 * 64 * ALDH;        // [d][key]

    const int blk = blockIdx.x;
    const int n = blk % NSPAT;
    const int h = (blk / NSPAT) % HEADS;
    const int b = blk / (NSPAT * HEADS);

    const int tid  = threadIdx.x;
    const int warp = tid >> 5;
    const int lane = tid & 31;
    const int g    = lane >> 2;
    const int t    = lane & 3;

    const size_t rowstride = (size_t)NSPAT * QKV_N;
    const size_t base = ((size_t)b * T_SEQ * NSPAT + n) * QKV_N + (size_t)h * HD;

    for (int idx = tid; idx < 64 * 32; idx += 128) {
        int tt = idx >> 5;               // token 0..63
        int d2 = idx & 31;               // half2 index 0..31
        const __half2* gp = (const __half2*)(qkv + base + (size_t)tt * rowstride);
        __half2 q2 = gp[d2];
        __half2 k2 = ((const __half2*)(qkv + base + (size_t)tt * rowstride + CDIM))[d2];
        __half2 v2 = ((const __half2*)(qkv + base + (size_t)tt * rowstride + 2 * CDIM))[d2];
        *(__half2*)&sQ[tt * ALDH + 2 * d2] = q2;
        *(__half2*)&sK[tt * ALDH + 2 * d2] = k2;
        sVt[(2 * d2 + 0) * ALDH + tt] = __low2half(v2);
        sVt[(2 * d2 + 1) * ALDH + tt] = __high2half(v2);
    }
    __syncthreads();

    const int m0 = warp * 16;
    const int i0 = m0 + g;
    const int i1 = m0 + g + 8;

    float s[8][4];
    #pragma unroll
    for (int nf = 0; nf < 8; nf++)
        #pragma unroll
        for (int c = 0; c < 4; c++) s[nf][c] = 0.0f;

    {
        const uint32_t* Qw = (const uint32_t*)sQ;
        const uint32_t* Kw = (const uint32_t*)sK;
        #pragma unroll
        for (int ks = 0; ks < 4; ks++) {
            uint32_t a[4];
            int w = i0 * ALDW + ks * 8 + t;
            a[0] = Qw[w];
            a[1] = Qw[w + 8 * ALDW];
            a[2] = Qw[w + 4];
            a[3] = Qw[w + 8 * ALDW + 4];
            #pragma unroll
            for (int nf = 0; nf < 8; nf++) {
                uint32_t bb[2];
                int wb = (nf * 8 + g) * ALDW + ks * 8 + t;
                bb[0] = Kw[wb];
                bb[1] = Kw[wb + 4];
                mma16816(s[nf], a, bb);
            }
        }
    }

    const float scale = 0.125f;
    float mx0 = -1e30f, mx1 = -1e30f;
    #pragma unroll
    for (int nf = 0; nf < 8; nf++) {
        int j0 = nf * 8 + 2 * t, j1 = j0 + 1;
        s[nf][0] = (j0 <= i0) ? s[nf][0] * scale : -1e30f;
        s[nf][1] = (j1 <= i0) ? s[nf][1] * scale : -1e30f;
        s[nf][2] = (j0 <= i1) ? s[nf][2] * scale : -1e30f;
        s[nf][3] = (j1 <= i1) ? s[nf][3] * scale : -1e30f;
        mx0 = fmaxf(mx0, fmaxf(s[nf][0], s[nf][1]));
        mx1 = fmaxf(mx1, fmaxf(s[nf][2], s[nf][3]));
    }
    mx0 = fmaxf(mx0, __shfl_xor_sync(0xffffffffu, mx0, 1));
    mx0 = fmaxf(mx0, __shfl_xor_sync(0xffffffffu, mx0, 2));
    mx1 = fmaxf(mx1, __shfl_xor_sync(0xffffffffu, mx1, 1));
    mx1 = fmaxf(mx1, __shfl_xor_sync(0xffffffffu, mx1, 2));

    float sum0 = 0.0f, sum1 = 0.0f;
    #pragma unroll
    for (int nf = 0; nf < 8; nf++) {
        s[nf][0] = __expf(s[nf][0] - mx0);
        s[nf][1] = __expf(s[nf][1] - mx0);
        s[nf][2] = __expf(s[nf][2] - mx1);
        s[nf][3] = __expf(s[nf][3] - mx1);
        sum0 += s[nf][0] + s[nf][1];
        sum1 += s[nf][2] + s[nf][3];
    }
    sum0 += __shfl_xor_sync(0xffffffffu, sum0, 1);
    sum0 += __shfl_xor_sync(0xffffffffu, sum0, 2);
    sum1 += __shfl_xor_sync(0xffffffffu, sum1, 1);
    sum1 += __shfl_xor_sync(0xffffffffu, sum1, 2);
    const float inv0 = 1.0f / sum0;
    const float inv1 = 1.0f / sum1;

    __syncwarp();
    __half* sP = sQ;
    #pragma unroll
    for (int nf = 0; nf < 8; nf++) {
        int jc = nf * 8 + 2 * t;
        *(__half2*)&sP[i0 * ALDH + jc] = __floats2half2_rn(s[nf][0] * inv0, s[nf][1] * inv0);
        *(__half2*)&sP[i1 * ALDH + jc] = __floats2half2_rn(s[nf][2] * inv1, s[nf][3] * inv1);
    }
    __syncwarp();

    float o[8][4];
    #pragma unroll
    for (int nf = 0; nf < 8; nf++)
        #pragma unroll
        for (int c = 0; c < 4; c++) o[nf][c] = 0.0f;

    {
        const uint32_t* Pw = (const uint32_t*)sP;
        const uint32_t* Vw = (const uint32_t*)sVt;
        #pragma unroll
        for (int ks = 0; ks < 4; ks++) {
            uint32_t a[4];
            int w = i0 * ALDW + ks * 8 + t;
            a[0] = Pw[w];
            a[1] = Pw[w + 8 * ALDW];
            a[2] = Pw[w + 4];
            a[3] = Pw[w + 8 * ALDW + 4];
            #pragma unroll
            for (int nf = 0; nf < 8; nf++) {
                uint32_t bb[2];
                int wb = (nf * 8 + g) * ALDW + ks * 8 + t;
                bb[0] = Vw[wb];
                bb[1] = Vw[wb + 4];
                mma16816(o[nf], a, bb);
            }
        }
    }

    #pragma unroll
    for (int nf = 0; nf < 8; nf++) {
        int col = nf * 8 + 2 * t;
        size_t a0 = (((size_t)b * T_SEQ + i0) * NSPAT + n) * CDIM + (size_t)h * HD + col;
        size_t a1 = (((size_t)b * T_SEQ + i1) * NSPAT + n) * CDIM + (size_t)h * HD + col;
        *(__half2*)&att[a0] = __floats2half2_rn(o[nf][0], o[nf][1]);
        *(__half2*)&att[a1] = __floats2half2_rn(o[nf][2], o[nf][3]);
    }
}

// ---------------------------------------------------------------------------
extern "C" void kernel_launch(void* const* d_in, const int* in_sizes, int n_in,
                              void* d_out, int out_size)
{
    const float* x      = (const float*)d_in[0];
    const float* w_qkv  = (const float*)d_in[1];
    const float* w_proj = (const float*)d_in[2];
    const float* b_proj = (const float*)d_in[3];
    float* out = (float*)d_out;

    __half *qkv_buf, *att_buf, *xh, *wqh, *wph;
    cudaGetSymbolAddress((void**)&qkv_buf, g_qkv);
    cudaGetSymbolAddress((void**)&att_buf, g_att);
    cudaGetSymbolAddress((void**)&xh, g_xh);
    cudaGetSymbolAddress((void**)&wqh, g_wqh);
    cudaGetSymbolAddress((void**)&wph, g_wph);

    static bool attr_done = false;
    if (!attr_done) {
        cudaFuncSetAttribute(gemm_h_kernel<true>,
                             cudaFuncAttributeMaxDynamicSharedMemorySize, G_SMEM);
        cudaFuncSetAttribute(gemm_h_kernel<false>,
                             cudaFuncAttributeMaxDynamicSharedMemorySize, G_SMEM);
        cudaFuncSetAttribute(attn_mma_kernel,
                             cudaFuncAttributeMaxDynamicSharedMemorySize, ATTN_SMEM);
        attr_done = true;
    }

    // 0) fp16 conversion prepasses
    {
        size_t n4 = (size_t)M_TOT * CDIM / 4;
        f2h_kernel<<<(unsigned)((n4 + 255) / 256), 256>>>(x, xh, n4);
        size_t wq4 = (size_t)QKV_N * CDIM / 4;
        f2h_kernel<<<(unsigned)((wq4 + 255) / 256), 256>>>(w_qkv, wqh, wq4);
        size_t wp4 = (size_t)CDIM * CDIM / 4;
        f2h_kernel<<<(unsigned)((wp4 + 255) / 256), 256>>>(w_proj, wph, wp4);
    }
    // 1) QKV GEMM (fp16 in, fp16 out): (50176 x 768) @ (2304 x 768)^T
    {
        dim3 grid(QKV_N / GBN, M_TOT / GBM);   // (18, 196)
        gemm_h_kernel<true><<<grid, 256, G_SMEM>>>(xh, wqh, (void*)qkv_buf, nullptr,
                                                   M_TOT, QKV_N, CDIM);
    }
    // 2) Attention (fp16 tensor-core)
    {
        dim3 grid(BATCH * HEADS * NSPAT);      // 9408
        attn_mma_kernel<<<grid, 128, ATTN_SMEM>>>(qkv_buf, att_buf);
    }
    // 3) Projection GEMM + fused bias (fp16 in, fp32 out)
    {
        dim3 grid(CDIM / GBN, M_TOT / GBM);    // (6, 196)
        gemm_h_kernel<false><<<grid, 256, G_SMEM>>>(att_buf, wph, (void*)out, b_proj,
                                                    M_TOT, CDIM, CDIM);
    }
}

// round 13
// speedup vs baseline: 1.0615x; 1.0615x over previous
#include <cuda_runtime.h>
#include <cuda_fp16.h>
#include <cstdint>

#define BATCH   4
#define T_SEQ   64
#define NSPAT   196
#define CDIM    768
#define HEADS   12
#define HD      64
#define M_TOT   (BATCH * T_SEQ * NSPAT)   // 50176
#define QKV_N   (3 * CDIM)                // 2304

// Scratch (device globals: allocation-free per harness rules)
__device__ __half g_qkv[(size_t)M_TOT * QKV_N];  // 231 MB
__device__ __half g_att[(size_t)M_TOT * CDIM];   // 77 MB
__device__ __half g_xh [(size_t)M_TOT * CDIM];   // 77 MB  (fp16 x)
__device__ __half g_wqh[(size_t)QKV_N * CDIM];   // fp16 w_qkv
__device__ __half g_wph[(size_t)CDIM * CDIM];    // fp16 w_proj

// ---------------------------------------------------------------------------
// helpers
// ---------------------------------------------------------------------------
__device__ __forceinline__ void cp_async16(uint32_t saddr, const void* gptr) {
    asm volatile("cp.async.cg.shared.global [%0], [%1], 16;\n" :: "r"(saddr), "l"(gptr));
}
__device__ __forceinline__ void cp_commit() {
    asm volatile("cp.async.commit_group;\n" ::: "memory");
}
__device__ __forceinline__ void cp_wait1() {
    asm volatile("cp.async.wait_group 1;\n" ::: "memory");
}
// D += A*B  (m16n8k16 fp16 inputs, fp32 accum)
__device__ __forceinline__ void mma16816(float* d, const uint32_t* a, const uint32_t* b) {
    asm volatile(
        "mma.sync.aligned.m16n8k16.row.col.f32.f16.f16.f32 "
        "{%0,%1,%2,%3}, {%4,%5,%6,%7}, {%8,%9}, {%0,%1,%2,%3};"
        : "+f"(d[0]), "+f"(d[1]), "+f"(d[2]), "+f"(d[3])
        : "r"(a[0]), "r"(a[1]), "r"(a[2]), "r"(a[3]), "r"(b[0]), "r"(b[1]));
}
// 4x 8x8 b16 matrices from shared
__device__ __forceinline__ void ldmx4(uint32_t& r0, uint32_t& r1, uint32_t& r2, uint32_t& r3,
                                      uint32_t saddr) {
    asm volatile("ldmatrix.sync.aligned.m8n8.x4.shared.b16 {%0,%1,%2,%3}, [%4];"
                 : "=r"(r0), "=r"(r1), "=r"(r2), "=r"(r3) : "r"(saddr));
}

// ---------------------------------------------------------------------------
// FP16 MMA GEMM: C[m][n] = sum_k A[m*K+k] * B[n*K+k] (+ bias[n])
// Block 128(m) x 128(n), BK=64, 3-stage cp.async, 256 threads = 8 warps (4x2),
// warp tile 32x64 = 2(m) x 8(n) frags; fragments via ldmatrix.x4.
// 2 CTAs/SM (two sync domains), 4 warps/SMSP. One barrier per K-block.
// ---------------------------------------------------------------------------
#define GBM 128
#define GBN 128
#define GBK 64
#define G_ROWB 144                               // bytes per smem row
#define STAGE_BYTES ((GBM + GBN) * G_ROWB)       // 36,864 B
#define G_STAGES 3
#define G_SMEM (G_STAGES * STAGE_BYTES)          // 110,592 B

template<bool HALF_OUT>
__global__ void __launch_bounds__(256, 2) gemm_h_kernel(
    const __half* __restrict__ A, const __half* __restrict__ B,
    void* __restrict__ Cv, const float* __restrict__ bias,
    int M, int N, int K)
{
    extern __shared__ char smem[];
    const uint32_t sbase = (uint32_t)__cvta_generic_to_shared(smem);

    const int n0 = blockIdx.x * GBN;     // N fastest -> weights L2-resident
    const int m0 = blockIdx.y * GBM;

    const int tid  = threadIdx.x;
    const int warp = tid >> 5;
    const int lane = tid & 31;
    const int wm   = warp >> 1;          // 0..3 -> rows wm*32
    const int wn   = warp & 1;           // 0..1 -> cols wn*64
    const int g    = lane >> 2;          // 0..7
    const int t    = lane & 3;           // 0..3
    const int quad = lane >> 3;          // 0..3 (ldmatrix address group)
    const int qr   = lane & 7;           // row within group

    // per-thread intra-stage ldmatrix offsets
    // A: matrices [rows, rows+8] x [k lo16B, k hi16B]
    const uint32_t a_off = (uint32_t)((wm * 32 + (quad & 1) * 8 + qr) * G_ROWB
                                      + (quad >> 1) * 16);
    // B: matrices [nblk, nblk+8] x [k lo16B, k hi16B]
    const uint32_t b_off = (uint32_t)(GBM * G_ROWB
                                      + (wn * 64 + (quad >> 1) * 8 + qr) * G_ROWB
                                      + (quad & 1) * 16);

    float acc[2][8][4];
    #pragma unroll
    for (int i = 0; i < 2; i++)
        #pragma unroll
        for (int j = 0; j < 8; j++)
            #pragma unroll
            for (int c = 0; c < 4; c++)
                acc[i][j][c] = 0.0f;

    const int NB = K / GBK;              // 12

    // stage loader: 256 rows x 8 chunks(16B) = 2048, 8 per thread
    auto issue_stage = [&](int kb, int s) {
        char* dst = smem + s * STAGE_BYTES;
        #pragma unroll
        for (int i = 0; i < 8; i++) {
            int id = tid + i * 256;              // 0..2047
            int r  = id >> 3;                    // 0..255
            int c  = id & 7;                     // 0..7 (8 halves each)
            const __half* gp = (r < GBM)
                ? A + (size_t)(m0 + r) * K + kb * GBK + c * 8
                : B + (size_t)(n0 + r - GBM) * K + kb * GBK + c * 8;
            uint32_t sa = (uint32_t)__cvta_generic_to_shared(dst + r * G_ROWB + c * 16);
            cp_async16(sa, gp);
        }
    };

    issue_stage(0, 0); cp_commit();
    issue_stage(1, 1); cp_commit();

    for (int kb = 0; kb < NB; kb++) {
        cp_wait1();            // stage kb resident
        __syncthreads();       // also orders all reads of slot (kb+2)%3's old
                               // contents (done at iter kb-1) before refill below

        if (kb + 2 < NB) issue_stage(kb + 2, (kb + 2) % 3);
        cp_commit();           // one group per iteration

        const uint32_t stg = sbase + (uint32_t)((kb % 3) * STAGE_BYTES);

        #pragma unroll
        for (int ks = 0; ks < 4; ks++) {
            uint32_t a[2][4], b[8][2];
            #pragma unroll
            for (int mf = 0; mf < 2; mf++)
                ldmx4(a[mf][0], a[mf][1], a[mf][2], a[mf][3],
                      stg + a_off + (uint32_t)(mf * 16 * G_ROWB + ks * 32));
            #pragma unroll
            for (int p = 0; p < 4; p++)
                ldmx4(b[2 * p][0], b[2 * p][1], b[2 * p + 1][0], b[2 * p + 1][1],
                      stg + b_off + (uint32_t)(p * 16 * G_ROWB + ks * 32));
            #pragma unroll
            for (int mf = 0; mf < 2; mf++)
                #pragma unroll
                for (int nf = 0; nf < 8; nf++)
                    mma16816(acc[mf][nf], a[mf], b[nf]);
        }
        // no tail barrier: next iteration's top barrier provides ordering
    }

    // epilogue: fused bias; half2 or float2 stores
    #pragma unroll
    for (int nf = 0; nf < 8; nf++) {
        int col = n0 + wn * 64 + nf * 8 + 2 * t;
        float bx = 0.0f, by = 0.0f;
        if (bias) { float2 bv = *(const float2*)&bias[col]; bx = bv.x; by = bv.y; }
        #pragma unroll
        for (int mf = 0; mf < 2; mf++) {
            int row = m0 + wm * 32 + mf * 16 + g;
            if (HALF_OUT) {
                __half* Ch = (__half*)Cv;
                *(__half2*)&Ch[(size_t)row * N + col] =
                    __floats2half2_rn(acc[mf][nf][0] + bx, acc[mf][nf][1] + by);
                *(__half2*)&Ch[(size_t)(row + 8) * N + col] =
                    __floats2half2_rn(acc[mf][nf][2] + bx, acc[mf][nf][3] + by);
            } else {
                float* Cf = (float*)Cv;
                *(float2*)&Cf[(size_t)row * N + col] =
                    make_float2(acc[mf][nf][0] + bx, acc[mf][nf][1] + by);
                *(float2*)&Cf[(size_t)(row + 8) * N + col] =
                    make_float2(acc[mf][nf][2] + bx, acc[mf][nf][3] + by);
            }
        }
    }
}

// ---------------------------------------------------------------------------
// fp32 -> fp16 conversion prepass
// ---------------------------------------------------------------------------
__global__ void __launch_bounds__(256) f2h_kernel(
    const float* __restrict__ in, __half* __restrict__ out, size_t n4)
{
    size_t i = (size_t)blockIdx.x * 256 + threadIdx.x;
    if (i < n4) {
        float4 v = ((const float4*)in)[i];
        ((__half2*)out)[2 * i + 0] = __floats2half2_rn(v.x, v.y);
        ((__half2*)out)[2 * i + 1] = __floats2half2_rn(v.z, v.w);
    }
}

// ---------------------------------------------------------------------------
// FP16 MMA causal attention per (b,h,n): T=64, hd=64.
// 128 threads = 4 warps; warp w owns query rows 16w..16w+15.
// ---------------------------------------------------------------------------
#define ALDH 72                       // halves per smem row
#define ALDW 36                       // words per row
#define ATTN_SMEM (3 * 64 * ALDH * 2) // 27,648 B

__global__ void __launch_bounds__(128) attn_mma_kernel(
    const __half* __restrict__ qkv, __half* __restrict__ att)
{
    extern __shared__ char smc[];
    __half* sQ  = (__half*)smc;              // [q][d]; reused as sP [q][j]
    __half* sK  = sQ + 64 * ALDH;            // [key][d]
    __half* sVt = sQ + 2 * 64 * ALDH;        // [d][key]

    const int blk = blockIdx.x;
    const int n = blk % NSPAT;
    const int h = (blk / NSPAT) % HEADS;
    const int b = blk / (NSPAT * HEADS);

    const int tid  = threadIdx.x;
    const int warp = tid >> 5;
    const int lane = tid & 31;
    const int g    = lane >> 2;
    const int t    = lane & 3;

    const size_t rowstride = (size_t)NSPAT * QKV_N;
    const size_t base = ((size_t)b * T_SEQ * NSPAT + n) * QKV_N + (size_t)h * HD;

    for (int idx = tid; idx < 64 * 32; idx += 128) {
        int tt = idx >> 5;               // token 0..63
        int d2 = idx & 31;               // half2 index 0..31
        const __half2* gp = (const __half2*)(qkv + base + (size_t)tt * rowstride);
        __half2 q2 = gp[d2];
        __half2 k2 = ((const __half2*)(qkv + base + (size_t)tt * rowstride + CDIM))[d2];
        __half2 v2 = ((const __half2*)(qkv + base + (size_t)tt * rowstride + 2 * CDIM))[d2];
        *(__half2*)&sQ[tt * ALDH + 2 * d2] = q2;
        *(__half2*)&sK[tt * ALDH + 2 * d2] = k2;
        sVt[(2 * d2 + 0) * ALDH + tt] = __low2half(v2);
        sVt[(2 * d2 + 1) * ALDH + tt] = __high2half(v2);
    }
    __syncthreads();

    const int m0 = warp * 16;
    const int i0 = m0 + g;
    const int i1 = m0 + g + 8;

    float s[8][4];
    #pragma unroll
    for (int nf = 0; nf < 8; nf++)
        #pragma unroll
        for (int c = 0; c < 4; c++) s[nf][c] = 0.0f;

    {
        const uint32_t* Qw = (const uint32_t*)sQ;
        const uint32_t* Kw = (const uint32_t*)sK;
        #pragma unroll
        for (int ks = 0; ks < 4; ks++) {
            uint32_t a[4];
            int w = i0 * ALDW + ks * 8 + t;
            a[0] = Qw[w];
            a[1] = Qw[w + 8 * ALDW];
            a[2] = Qw[w + 4];
            a[3] = Qw[w + 8 * ALDW + 4];
            #pragma unroll
            for (int nf = 0; nf < 8; nf++) {
                uint32_t bb[2];
                int wb = (nf * 8 + g) * ALDW + ks * 8 + t;
                bb[0] = Kw[wb];
                bb[1] = Kw[wb + 4];
                mma16816(s[nf], a, bb);
            }
        }
    }

    const float scale = 0.125f;
    float mx0 = -1e30f, mx1 = -1e30f;
    #pragma unroll
    for (int nf = 0; nf < 8; nf++) {
        int j0 = nf * 8 + 2 * t, j1 = j0 + 1;
        s[nf][0] = (j0 <= i0) ? s[nf][0] * scale : -1e30f;
        s[nf][1] = (j1 <= i0) ? s[nf][1] * scale : -1e30f;
        s[nf][2] = (j0 <= i1) ? s[nf][2] * scale : -1e30f;
        s[nf][3] = (j1 <= i1) ? s[nf][3] * scale : -1e30f;
        mx0 = fmaxf(mx0, fmaxf(s[nf][0], s[nf][1]));
        mx1 = fmaxf(mx1, fmaxf(s[nf][2], s[nf][3]));
    }
    mx0 = fmaxf(mx0, __shfl_xor_sync(0xffffffffu, mx0, 1));
    mx0 = fmaxf(mx0, __shfl_xor_sync(0xffffffffu, mx0, 2));
    mx1 = fmaxf(mx1, __shfl_xor_sync(0xffffffffu, mx1, 1));
    mx1 = fmaxf(mx1, __shfl_xor_sync(0xffffffffu, mx1, 2));

    float sum0 = 0.0f, sum1 = 0.0f;
    #pragma unroll
    for (int nf = 0; nf < 8; nf++) {
        s[nf][0] = __expf(s[nf][0] - mx0);
        s[nf][1] = __expf(s[nf][1] - mx0);
        s[nf][2] = __expf(s[nf][2] - mx1);
        s[nf][3] = __expf(s[nf][3] - mx1);
        sum0 += s[nf][0] + s[nf][1];
        sum1 += s[nf][2] + s[nf][3];
    }
    sum0 += __shfl_xor_sync(0xffffffffu, sum0, 1);
    sum0 += __shfl_xor_sync(0xffffffffu, sum0, 2);
    sum1 += __shfl_xor_sync(0xffffffffu, sum1, 1);
    sum1 += __shfl_xor_sync(0xffffffffu, sum1, 2);
    const float inv0 = 1.0f / sum0;
    const float inv1 = 1.0f / sum1;

    __syncwarp();
    __half* sP = sQ;
    #pragma unroll
    for (int nf = 0; nf < 8; nf++) {
        int jc = nf * 8 + 2 * t;
        *(__half2*)&sP[i0 * ALDH + jc] = __floats2half2_rn(s[nf][0] * inv0, s[nf][1] * inv0);
        *(__half2*)&sP[i1 * ALDH + jc] = __floats2half2_rn(s[nf][2] * inv1, s[nf][3] * inv1);
    }
    __syncwarp();

    float o[8][4];
    #pragma unroll
    for (int nf = 0; nf < 8; nf++)
        #pragma unroll
        for (int c = 0; c < 4; c++) o[nf][c] = 0.0f;

    {
        const uint32_t* Pw = (const uint32_t*)sP;
        const uint32_t* Vw = (const uint32_t*)sVt;
        #pragma unroll
        for (int ks = 0; ks < 4; ks++) {
            uint32_t a[4];
            int w = i0 * ALDW + ks * 8 + t;
            a[0] = Pw[w];
            a[1] = Pw[w + 8 * ALDW];
            a[2] = Pw[w + 4];
            a[3] = Pw[w + 8 * ALDW + 4];
            #pragma unroll
            for (int nf = 0; nf < 8; nf++) {
                uint32_t bb[2];
                int wb = (nf * 8 + g) * ALDW + ks * 8 + t;
                bb[0] = Vw[wb];
                bb[1] = Vw[wb + 4];
                mma16816(o[nf], a, bb);
            }
        }
    }

    #pragma unroll
    for (int nf = 0; nf < 8; nf++) {
        int col = nf * 8 + 2 * t;
        size_t a0 = (((size_t)b * T_SEQ + i0) * NSPAT + n) * CDIM + (size_t)h * HD + col;
        size_t a1 = (((size_t)b * T_SEQ + i1) * NSPAT + n) * CDIM + (size_t)h * HD + col;
        *(__half2*)&att[a0] = __floats2half2_rn(o[nf][0], o[nf][1]);
        *(__half2*)&att[a1] = __floats2half2_rn(o[nf][2], o[nf][3]);
    }
}

// ---------------------------------------------------------------------------
extern "C" void kernel_launch(void* const* d_in, const int* in_sizes, int n_in,
                              void* d_out, int out_size)
{
    const float* x      = (const float*)d_in[0];
    const float* w_qkv  = (const float*)d_in[1];
    const float* w_proj = (const float*)d_in[2];
    const float* b_proj = (const float*)d_in[3];
    float* out = (float*)d_out;

    __half *qkv_buf, *att_buf, *xh, *wqh, *wph;
    cudaGetSymbolAddress((void**)&qkv_buf, g_qkv);
    cudaGetSymbolAddress((void**)&att_buf, g_att);
    cudaGetSymbolAddress((void**)&xh, g_xh);
    cudaGetSymbolAddress((void**)&wqh, g_wqh);
    cudaGetSymbolAddress((void**)&wph, g_wph);

    static bool attr_done = false;
    if (!attr_done) {
        cudaFuncSetAttribute(gemm_h_kernel<true>,
                             cudaFuncAttributeMaxDynamicSharedMemorySize, G_SMEM);
        cudaFuncSetAttribute(gemm_h_kernel<false>,
                             cudaFuncAttributeMaxDynamicSharedMemorySize, G_SMEM);
        cudaFuncSetAttribute(attn_mma_kernel,
                             cudaFuncAttributeMaxDynamicSharedMemorySize, ATTN_SMEM);
        attr_done = true;
    }

    // 0) fp16 conversion prepasses
    {
        size_t n4 = (size_t)M_TOT * CDIM / 4;
        f2h_kernel<<<(unsigned)((n4 + 255) / 256), 256>>>(x, xh, n4);
        size_t wq4 = (size_t)QKV_N * CDIM / 4;
        f2h_kernel<<<(unsigned)((wq4 + 255) / 256), 256>>>(w_qkv, wqh, wq4);
        size_t wp4 = (size_t)CDIM * CDIM / 4;
        f2h_kernel<<<(unsigned)((wp4 + 255) / 256), 256>>>(w_proj, wph, wp4);
    }
    // 1) QKV GEMM (fp16 in, fp16 out): (50176 x 768) @ (2304 x 768)^T
    {
        dim3 grid(QKV_N / GBN, M_TOT / GBM);   // (18, 392)
        gemm_h_kernel<true><<<grid, 256, G_SMEM>>>(xh, wqh, (void*)qkv_buf, nullptr,
                                                   M_TOT, QKV_N, CDIM);
    }
    // 2) Attention (fp16 tensor-core)
    {
        dim3 grid(BATCH * HEADS * NSPAT);      // 9408
        attn_mma_kernel<<<grid, 128, ATTN_SMEM>>>(qkv_buf, att_buf);
    }
    // 3) Projection GEMM + fused bias (fp16 in, fp32 out)
    {
        dim3 grid(CDIM / GBN, M_TOT / GBM);    // (6, 392)
        gemm_h_kernel<false><<<grid, 256, G_SMEM>>>(att_buf, wph, (void*)out, b_proj,
                                                    M_TOT, CDIM, CDIM);
    }
}

// round 15
// speedup vs baseline: 1.1553x; 1.0883x over previous
#include <cuda_runtime.h>
#include <cuda_fp16.h>
#include <cstdint>

#define BATCH   4
#define T_SEQ   64
#define NSPAT   196
#define CDIM    768
#define HEADS   12
#define HD      64
#define M_TOT   (BATCH * T_SEQ * NSPAT)   // 50176
#define QKV_N   (3 * CDIM)                // 2304

// Scratch (device globals: allocation-free per harness rules)
__device__ __half g_qkv[(size_t)M_TOT * QKV_N];  // 231 MB
__device__ __half g_att[(size_t)M_TOT * CDIM];   // 77 MB
__device__ __half g_xh [(size_t)M_TOT * CDIM];   // 77 MB  (fp16 x)
__device__ __half g_wqh[(size_t)QKV_N * CDIM];   // fp16 w_qkv
__device__ __half g_wph[(size_t)CDIM * CDIM];    // fp16 w_proj

// ---------------------------------------------------------------------------
// helpers
// ---------------------------------------------------------------------------
__device__ __forceinline__ void cp_async16(uint32_t saddr, const void* gptr) {
    asm volatile("cp.async.cg.shared.global [%0], [%1], 16;\n" :: "r"(saddr), "l"(gptr));
}
__device__ __forceinline__ void mbar_init(uint32_t mbar, uint32_t cnt) {
    asm volatile("mbarrier.init.shared.b64 [%0], %1;" :: "r"(mbar), "r"(cnt) : "memory");
}
__device__ __forceinline__ void mbar_arrive(uint32_t mbar) {
    asm volatile("mbarrier.arrive.shared.b64 _, [%0];" :: "r"(mbar) : "memory");
}
// .noinc: the deferred arrive consumes one of the pre-initialized expected
// arrivals (default variant increments pending first -> net zero -> deadlock)
__device__ __forceinline__ void cp_async_mbar_arrive_noinc(uint32_t mbar) {
    asm volatile("cp.async.mbarrier.arrive.noinc.shared.b64 [%0];" :: "r"(mbar) : "memory");
}
__device__ __forceinline__ void mbar_wait(uint32_t mbar, uint32_t parity) {
    asm volatile(
        "{\n\t.reg .pred P;\n\t"
        "WL_%=:\n\t"
        "mbarrier.try_wait.parity.shared.b64 P, [%0], %1;\n\t"
        "@P bra WD_%=;\n\t"
        "bra WL_%=;\n\t"
        "WD_%=:\n\t}"
        :: "r"(mbar), "r"(parity) : "memory");
}
// D += A*B  (m16n8k16 fp16 inputs, fp32 accum)
__device__ __forceinline__ void mma16816(float* d, const uint32_t* a, const uint32_t* b) {
    asm volatile(
        "mma.sync.aligned.m16n8k16.row.col.f32.f16.f16.f32 "
        "{%0,%1,%2,%3}, {%4,%5,%6,%7}, {%8,%9}, {%0,%1,%2,%3};"
        : "+f"(d[0]), "+f"(d[1]), "+f"(d[2]), "+f"(d[3])
        : "r"(a[0]), "r"(a[1]), "r"(a[2]), "r"(a[3]), "r"(b[0]), "r"(b[1]));
}
// 4x 8x8 b16 matrices from shared
__device__ __forceinline__ void ldmx4(uint32_t& r0, uint32_t& r1, uint32_t& r2, uint32_t& r3,
                                      uint32_t saddr) {
    asm volatile("ldmatrix.sync.aligned.m8n8.x4.shared.b16 {%0,%1,%2,%3}, [%4];"
                 : "=r"(r0), "=r"(r1), "=r"(r2), "=r"(r3) : "r"(saddr));
}

// ---------------------------------------------------------------------------
// Warp-specialized FP16 GEMM: C[m][n] = sum_k A[m*K+k]*B[n*K+k] (+ bias[n])
// Block 128x128, BK=64, 3-stage mbarrier ring. 160 threads:
//   warps 0-3: consumers, warp tile 64x64 (2x2 grid), ldmatrix + double-buffer
//   warp 4:    producer, all cp.async traffic
// No __syncthreads in the mainloop; 2 CTAs/SM.
// ---------------------------------------------------------------------------
#define GBM 128
#define GBN 128
#define GBK 64
#define G_ROWB 144                               // bytes per smem row
#define STAGE_BYTES ((GBM + GBN) * G_ROWB)       // 36,864 B
#define G_STAGE0 1024                            // barriers live below this
#define G_SMEM (G_STAGE0 + 3 * STAGE_BYTES)      // 111,616 B

template<bool HALF_OUT>
__global__ void __launch_bounds__(160, 2) gemm_ws_kernel(
    const __half* __restrict__ A, const __half* __restrict__ B,
    void* __restrict__ Cv, const float* __restrict__ bias,
    int M, int N, int K)
{
    extern __shared__ char smem[];
    const uint32_t sbase = (uint32_t)__cvta_generic_to_shared(smem);
    auto fullb  = [&](int s) { return sbase + (uint32_t)(s * 16); };
    auto emptyb = [&](int s) { return sbase + (uint32_t)(s * 16 + 8); };

    const int n0 = blockIdx.x * GBN;     // N fastest -> weights L2-resident
    const int m0 = blockIdx.y * GBM;

    const int tid  = threadIdx.x;
    const int warp = tid >> 5;
    const int lane = tid & 31;
    const int NB = K / GBK;              // 12

    if (tid == 0) {
        #pragma unroll
        for (int s = 0; s < 3; s++) {
            mbar_init(fullb(s), 32);     // one deferred arrive per producer lane
            mbar_init(emptyb(s), 4);     // one arrive per consumer warp
        }
    }
    __syncthreads();                     // only CTA barrier in the kernel

    if (warp == 4) {
        // ---------------- producer ----------------
        const int rA   = lane >> 3;              // 0..3 (row residue)
        const int cH   = (lane & 7) * 8;         // gmem half offset
        const uint32_t dByte = (uint32_t)(rA * G_ROWB + (lane & 7) * 16);
        for (int kb = 0; kb < NB; kb++) {
            const int s  = kb % 3;
            const int ph = (kb / 3) & 1;
            mbar_wait(emptyb(s), ph ^ 1);        // first pass free
            const uint32_t dst = sbase + G_STAGE0 + (uint32_t)(s * STAGE_BYTES) + dByte;
            const __half* Ag = A + (size_t)(m0 + rA) * K + kb * GBK + cH;
            const __half* Bg = B + (size_t)(n0 + rA) * K + kb * GBK + cH;
            #pragma unroll 8
            for (int i = 0; i < 32; i++)
                cp_async16(dst + (uint32_t)(i * 4 * G_ROWB), Ag + (size_t)(4 * i) * K);
            #pragma unroll 8
            for (int i = 0; i < 32; i++)
                cp_async16(dst + (uint32_t)(GBM * G_ROWB + i * 4 * G_ROWB),
                           Bg + (size_t)(4 * i) * K);
            cp_async_mbar_arrive_noinc(fullb(s)); // full[s] flips when data lands
        }
        return;
    }

    // ---------------- consumers (warps 0..3) ----------------
    const int wm   = warp >> 1;          // 0..1 -> rows wm*64
    const int wn   = warp & 1;           // 0..1 -> cols wn*64
    const int g    = lane >> 2;          // 0..7
    const int t    = lane & 3;           // 0..3
    const int quad = lane >> 3;          // ldmatrix address group
    const int qr   = lane & 7;

    const uint32_t a_off = (uint32_t)((wm * 64 + (quad & 1) * 8 + qr) * G_ROWB
                                      + (quad >> 1) * 16);
    const uint32_t b_off = (uint32_t)(GBM * G_ROWB
                                      + (wn * 64 + (quad >> 1) * 8 + qr) * G_ROWB
                                      + (quad & 1) * 16);

    float acc[4][8][4];
    #pragma unroll
    for (int i = 0; i < 4; i++)
        #pragma unroll
        for (int j = 0; j < 8; j++)
            #pragma unroll
            for (int c = 0; c < 4; c++)
                acc[i][j][c] = 0.0f;

    auto load_a = [&](uint32_t stg, int ks, uint32_t a[4][4]) {
        #pragma unroll
        for (int mf = 0; mf < 4; mf++)
            ldmx4(a[mf][0], a[mf][1], a[mf][2], a[mf][3],
                  stg + a_off + (uint32_t)(mf * 16 * G_ROWB + ks * 32));
    };
    auto load_b = [&](uint32_t stg, int ks, uint32_t b[8][2]) {
        #pragma unroll
        for (int p = 0; p < 4; p++)
            ldmx4(b[2 * p][0], b[2 * p][1], b[2 * p + 1][0], b[2 * p + 1][1],
                  stg + b_off + (uint32_t)(p * 16 * G_ROWB + ks * 32));
    };

    for (int kb = 0; kb < NB; kb++) {
        const int s  = kb % 3;
        const int ph = (kb / 3) & 1;
        mbar_wait(fullb(s), ph);
        const uint32_t stg = sbase + G_STAGE0 + (uint32_t)(s * STAGE_BYTES);

        uint32_t a0[4][4], b0[8][2], a1[4][4], b1[8][2];
        load_a(stg, 0, a0); load_b(stg, 0, b0);
        #pragma unroll
        for (int ks = 0; ks < 4; ks += 2) {
            if (ks + 1 < 4) { load_a(stg, ks + 1, a1); load_b(stg, ks + 1, b1); }
            #pragma unroll
            for (int mf = 0; mf < 4; mf++)
                #pragma unroll
                for (int nf = 0; nf < 8; nf++)
                    mma16816(acc[mf][nf], a0[mf], b0[nf]);
            if (ks + 2 < 4) { load_a(stg, ks + 2, a0); load_b(stg, ks + 2, b0); }
            if (ks + 1 < 4) {
                #pragma unroll
                for (int mf = 0; mf < 4; mf++)
                    #pragma unroll
                    for (int nf = 0; nf < 8; nf++)
                        mma16816(acc[mf][nf], a1[mf], b1[nf]);
            }
        }
        if (lane == 0) mbar_arrive(emptyb(s));   // stage free for refill
    }

    // epilogue: fused bias; half2 or float2 stores
    #pragma unroll
    for (int nf = 0; nf < 8; nf++) {
        int col = n0 + wn * 64 + nf * 8 + 2 * t;
        float bx = 0.0f, by = 0.0f;
        if (bias) { float2 bv = *(const float2*)&bias[col]; bx = bv.x; by = bv.y; }
        #pragma unroll
        for (int mf = 0; mf < 4; mf++) {
            int row = m0 + wm * 64 + mf * 16 + g;
            if (HALF_OUT) {
                __half* Ch = (__half*)Cv;
                *(__half2*)&Ch[(size_t)row * N + col] =
                    __floats2half2_rn(acc[mf][nf][0] + bx, acc[mf][nf][1] + by);
                *(__half2*)&Ch[(size_t)(row + 8) * N + col] =
                    __floats2half2_rn(acc[mf][nf][2] + bx, acc[mf][nf][3] + by);
            } else {
                float* Cf = (float*)Cv;
                *(float2*)&Cf[(size_t)row * N + col] =
                    make_float2(acc[mf][nf][0] + bx, acc[mf][nf][1] + by);
                *(float2*)&Cf[(size_t)(row + 8) * N + col] =
                    make_float2(acc[mf][nf][2] + bx, acc[mf][nf][3] + by);
            }
        }
    }
}

// ---------------------------------------------------------------------------
// fp32 -> fp16 conversion prepass
// ---------------------------------------------------------------------------
__global__ void __launch_bounds__(256) f2h_kernel(
    const float* __restrict__ in, __half* __restrict__ out, size_t n4)
{
    size_t i = (size_t)blockIdx.x * 256 + threadIdx.x;
    if (i < n4) {
        float4 v = ((const float4*)in)[i];
        ((__half2*)out)[2 * i + 0] = __floats2half2_rn(v.x, v.y);
        ((__half2*)out)[2 * i + 1] = __floats2half2_rn(v.z, v.w);
    }
}

// ---------------------------------------------------------------------------
// FP16 MMA causal attention per (b,h,n): T=64, hd=64.
// 128 threads = 4 warps; warp w owns query rows 16w..16w+15.
// ---------------------------------------------------------------------------
#define ALDH 72                       // halves per smem row
#define ALDW 36                       // words per row
#define ATTN_SMEM (3 * 64 * ALDH * 2) // 27,648 B

__global__ void __launch_bounds__(128) attn_mma_kernel(
    const __half* __restrict__ qkv, __half* __restrict__ att)
{
    extern __shared__ char smc[];
    __half* sQ  = (__half*)smc;              // [q][d]; reused as sP [q][j]
    __half* sK  = sQ + 64 * ALDH;            // [key][d]
    __half* sVt = sQ + 2 * 64 * ALDH;        // [d][key]

    const int blk = blockIdx.x;
    const int n = blk % NSPAT;
    const int h = (blk / NSPAT) % HEADS;
    const int b = blk / (NSPAT * HEADS);

    const int tid  = threadIdx.x;
    const int warp = tid >> 5;
    const int lane = tid & 31;
    const int g    = lane >> 2;
    const int t    = lane & 3;

    const size_t rowstride = (size_t)NSPAT * QKV_N;
    const size_t base = ((size_t)b * T_SEQ * NSPAT + n) * QKV_N + (size_t)h * HD;

    for (int idx = tid; idx < 64 * 32; idx += 128) {
        int tt = idx >> 5;               // token 0..63
        int d2 = idx & 31;               // half2 index 0..31
        const __half2* gp = (const __half2*)(qkv + base + (size_t)tt * rowstride);
        __half2 q2 = gp[d2];
        __half2 k2 = ((const __half2*)(qkv + base + (size_t)tt * rowstride + CDIM))[d2];
        __half2 v2 = ((const __half2*)(qkv + base + (size_t)tt * rowstride + 2 * CDIM))[d2];
        *(__half2*)&sQ[tt * ALDH + 2 * d2] = q2;
        *(__half2*)&sK[tt * ALDH + 2 * d2] = k2;
        sVt[(2 * d2 + 0) * ALDH + tt] = __low2half(v2);
        sVt[(2 * d2 + 1) * ALDH + tt] = __high2half(v2);
    }
    __syncthreads();

    const int m0 = warp * 16;
    const int i0 = m0 + g;
    const int i1 = m0 + g + 8;

    float s[8][4];
    #pragma unroll
    for (int nf = 0; nf < 8; nf++)
        #pragma unroll
        for (int c = 0; c < 4; c++) s[nf][c] = 0.0f;

    {
        const uint32_t* Qw = (const uint32_t*)sQ;
        const uint32_t* Kw = (const uint32_t*)sK;
        #pragma unroll
        for (int ks = 0; ks < 4; ks++) {
            uint32_t a[4];
            int w = i0 * ALDW + ks * 8 + t;
            a[0] = Qw[w];
            a[1] = Qw[w + 8 * ALDW];
            a[2] = Qw[w + 4];
            a[3] = Qw[w + 8 * ALDW + 4];
            #pragma unroll
            for (int nf = 0; nf < 8; nf++) {
                uint32_t bb[2];
                int wb = (nf * 8 + g) * ALDW + ks * 8 + t;
                bb[0] = Kw[wb];
                bb[1] = Kw[wb + 4];
                mma16816(s[nf], a, bb);
            }
        }
    }

    const float scale = 0.125f;
    float mx0 = -1e30f, mx1 = -1e30f;
    #pragma unroll
    for (int nf = 0; nf < 8; nf++) {
        int j0 = nf * 8 + 2 * t, j1 = j0 + 1;
        s[nf][0] = (j0 <= i0) ? s[nf][0] * scale : -1e30f;
        s[nf][1] = (j1 <= i0) ? s[nf][1] * scale : -1e30f;
        s[nf][2] = (j0 <= i1) ? s[nf][2] * scale : -1e30f;
        s[nf][3] = (j1 <= i1) ? s[nf][3] * scale : -1e30f;
        mx0 = fmaxf(mx0, fmaxf(s[nf][0], s[nf][1]));
        mx1 = fmaxf(mx1, fmaxf(s[nf][2], s[nf][3]));
    }
    mx0 = fmaxf(mx0, __shfl_xor_sync(0xffffffffu, mx0, 1));
    mx0 = fmaxf(mx0, __shfl_xor_sync(0xffffffffu, mx0, 2));
    mx1 = fmaxf(mx1, __shfl_xor_sync(0xffffffffu, mx1, 1));
    mx1 = fmaxf(mx1, __shfl_xor_sync(0xffffffffu, mx1, 2));

    float sum0 = 0.0f, sum1 = 0.0f;
    #pragma unroll
    for (int nf = 0; nf < 8; nf++) {
        s[nf][0] = __expf(s[nf][0] - mx0);
        s[nf][1] = __expf(s[nf][1] - mx0);
        s[nf][2] = __expf(s[nf][2] - mx1);
        s[nf][3] = __expf(s[nf][3] - mx1);
        sum0 += s[nf][0] + s[nf][1];
        sum1 += s[nf][2] + s[nf][3];
    }
    sum0 += __shfl_xor_sync(0xffffffffu, sum0, 1);
    sum0 += __shfl_xor_sync(0xffffffffu, sum0, 2);
    sum1 += __shfl_xor_sync(0xffffffffu, sum1, 1);
    sum1 += __shfl_xor_sync(0xffffffffu, sum1, 2);
    const float inv0 = 1.0f / sum0;
    const float inv1 = 1.0f / sum1;

    __syncwarp();
    __half* sP = sQ;
    #pragma unroll
    for (int nf = 0; nf < 8; nf++) {
        int jc = nf * 8 + 2 * t;
        *(__half2*)&sP[i0 * ALDH + jc] = __floats2half2_rn(s[nf][0] * inv0, s[nf][1] * inv0);
        *(__half2*)&sP[i1 * ALDH + jc] = __floats2half2_rn(s[nf][2] * inv1, s[nf][3] * inv1);
    }
    __syncwarp();

    float o[8][4];
    #pragma unroll
    for (int nf = 0; nf < 8; nf++)
        #pragma unroll
        for (int c = 0; c < 4; c++) o[nf][c] = 0.0f;

    {
        const uint32_t* Pw = (const uint32_t*)sP;
        const uint32_t* Vw = (const uint32_t*)sVt;
        #pragma unroll
        for (int ks = 0; ks < 4; ks++) {
            uint32_t a[4];
            int w = i0 * ALDW + ks * 8 + t;
            a[0] = Pw[w];
            a[1] = Pw[w + 8 * ALDW];
            a[2] = Pw[w + 4];
            a[3] = Pw[w + 8 * ALDW + 4];
            #pragma unroll
            for (int nf = 0; nf < 8; nf++) {
                uint32_t bb[2];
                int wb = (nf * 8 + g) * ALDW + ks * 8 + t;
                bb[0] = Vw[wb];
                bb[1] = Vw[wb + 4];
                mma16816(o[nf], a, bb);
            }
        }
    }

    #pragma unroll
    for (int nf = 0; nf < 8; nf++) {
        int col = nf * 8 + 2 * t;
        size_t a0 = (((size_t)b * T_SEQ + i0) * NSPAT + n) * CDIM + (size_t)h * HD + col;
        size_t a1 = (((size_t)b * T_SEQ + i1) * NSPAT + n) * CDIM + (size_t)h * HD + col;
        *(__half2*)&att[a0] = __floats2half2_rn(o[nf][0], o[nf][1]);
        *(__half2*)&att[a1] = __floats2half2_rn(o[nf][2], o[nf][3]);
    }
}

// ---------------------------------------------------------------------------
extern "C" void kernel_launch(void* const* d_in, const int* in_sizes, int n_in,
                              void* d_out, int out_size)
{
    const float* x      = (const float*)d_in[0];
    const float* w_qkv  = (const float*)d_in[1];
    const float* w_proj = (const float*)d_in[2];
    const float* b_proj = (const float*)d_in[3];
    float* out = (float*)d_out;

    __half *qkv_buf, *att_buf, *xh, *wqh, *wph;
    cudaGetSymbolAddress((void**)&qkv_buf, g_qkv);
    cudaGetSymbolAddress((void**)&att_buf, g_att);
    cudaGetSymbolAddress((void**)&xh, g_xh);
    cudaGetSymbolAddress((void**)&wqh, g_wqh);
    cudaGetSymbolAddress((void**)&wph, g_wph);

    static bool attr_done = false;
    if (!attr_done) {
        cudaFuncSetAttribute(gemm_ws_kernel<true>,
                             cudaFuncAttributeMaxDynamicSharedMemorySize, G_SMEM);
        cudaFuncSetAttribute(gemm_ws_kernel<false>,
                             cudaFuncAttributeMaxDynamicSharedMemorySize, G_SMEM);
        cudaFuncSetAttribute(attn_mma_kernel,
                             cudaFuncAttributeMaxDynamicSharedMemorySize, ATTN_SMEM);
        attr_done = true;
    }

    // 0) fp16 conversion prepasses
    {
        size_t n4 = (size_t)M_TOT * CDIM / 4;
        f2h_kernel<<<(unsigned)((n4 + 255) / 256), 256>>>(x, xh, n4);
        size_t wq4 = (size_t)QKV_N * CDIM / 4;
        f2h_kernel<<<(unsigned)((wq4 + 255) / 256), 256>>>(w_qkv, wqh, wq4);
        size_t wp4 = (size_t)CDIM * CDIM / 4;
        f2h_kernel<<<(unsigned)((wp4 + 255) / 256), 256>>>(w_proj, wph, wp4);
    }
    // 1) QKV GEMM (fp16 in, fp16 out): (50176 x 768) @ (2304 x 768)^T
    {
        dim3 grid(QKV_N / GBN, M_TOT / GBM);   // (18, 392)
        gemm_ws_kernel<true><<<grid, 160, G_SMEM>>>(xh, wqh, (void*)qkv_buf, nullptr,
                                                    M_TOT, QKV_N, CDIM);
    }
    // 2) Attention (fp16 tensor-core)
    {
        dim3 grid(BATCH * HEADS * NSPAT);      // 9408
        attn_mma_kernel<<<grid, 128, ATTN_SMEM>>>(qkv_buf, att_buf);
    }
    // 3) Projection GEMM + fused bias (fp16 in, fp32 out)
    {
        dim3 grid(CDIM / GBN, M_TOT / GBM);    // (6, 392)
        gemm_ws_kernel<false><<<grid, 160, G_SMEM>>>(att_buf, wph, (void*)out, b_proj,
                                                     M_TOT, CDIM, CDIM);
    }
}